// round 2
// baseline (speedup 1.0000x reference)
#include <cuda_runtime.h>

#define QW   12
#define DIMS 4096
#define NT   128      // threads per CTA (4 warps)
#define V    32       // amplitudes per thread (k bits 0..4)

// s (12 bits) = t*32 + k ; bit p of s:  p in [0,5) -> k bit p (register-local)
//                                       p in [5,10) -> lane bit p-5 (shuffle)
//                                       p in [10,12) -> warp bit p-10 (smem)
// wire j (0 = MSB in reference) <-> bit position p = 11 - j

__device__ __forceinline__ float2 cmulf(float2 a, float2 b) {
    return make_float2(fmaf(a.x, b.x, -a.y * b.y), fmaf(a.x, b.y, a.y * b.x));
}

struct Sm {
    float  sbuf[DIMS * 2];   // 32KB: image load + warp-gate exchange buffer
    float2 eK[32];           // per-diag-slot table over k bits
    float2 csT[2][6][12];    // (cos, sin)(theta/2) per block n, group g, wire
    float  aS[2][6][12];     // static (weight-only) alpha per diag slot, per wire
    float  ang[QW];          // current circuit inputs / expvals
    float  red[4 * QW];      // cross-warp reduction scratch
    float  cwS[12 * 9];
    float  cbS[12];
};

template<int M>
__device__ __forceinline__ void ry_local(float2* amp, float2 cs) {
    const float c = cs.x, s = cs.y;
#pragma unroll
    for (int k = 0; k < V; k++) {
        if (!(k & M)) {
            float2 a = amp[k], b = amp[k | M];
            amp[k]     = make_float2(fmaf(c, a.x, -s * b.x), fmaf(c, a.y, -s * b.y));
            amp[k | M] = make_float2(fmaf(s, a.x,  c * b.x), fmaf(s, a.y,  c * b.y));
        }
    }
}

__device__ __forceinline__ void ry_lane(float2* amp, int msk, float2 cs, int lane) {
    const float c  = cs.x;
    const float ss = (lane & msk) ? cs.y : -cs.y;
#pragma unroll
    for (int k = 0; k < V; k++) {
        float ox = __shfl_xor_sync(0xffffffffu, amp[k].x, msk);
        float oy = __shfl_xor_sync(0xffffffffu, amp[k].y, msk);
        amp[k].x = fmaf(c, amp[k].x, ss * ox);
        amp[k].y = fmaf(c, amp[k].y, ss * oy);
    }
}

__device__ __forceinline__ void ry_warp(float2* amp, int msk, float2 cs, int t, float* sb) {
    float2* buf = (float2*)sb;
#pragma unroll
    for (int k = 0; k < V; k++) buf[k * NT + t] = amp[k];
    __syncthreads();
    const int   tp = t ^ msk;
    const float c  = cs.x;
    const float ss = (t & msk) ? cs.y : -cs.y;
#pragma unroll
    for (int k = 0; k < V; k++) {
        float2 o = buf[k * NT + tp];
        amp[k].x = fmaf(c, amp[k].x, ss * o.x);
        amp[k].y = fmaf(c, amp[k].y, ss * o.y);
    }
    __syncthreads();
}

// reduce 12 per-thread partials across the CTA into sm.ang
__device__ __forceinline__ void reduce12(Sm& sm, float* part, int t, int lane,
                                         float scale, bool addBias) {
#pragma unroll
    for (int j = 0; j < QW; j++) {
        float v = part[j];
        v += __shfl_down_sync(0xffffffffu, v, 16);
        v += __shfl_down_sync(0xffffffffu, v, 8);
        v += __shfl_down_sync(0xffffffffu, v, 4);
        v += __shfl_down_sync(0xffffffffu, v, 2);
        v += __shfl_down_sync(0xffffffffu, v, 1);
        if (lane == 0) sm.red[(t >> 5) * QW + j] = v;
    }
    __syncthreads();
    if (t < QW) {
        float v = sm.red[t] + sm.red[QW + t] + sm.red[2 * QW + t] + sm.red[3 * QW + t];
        v *= scale;
        if (addBias) v += sm.cbS[t];
        sm.ang[t] = v;
    }
    __syncthreads();
}

__global__ void __launch_bounds__(NT) qiddm_kernel(
    const float* __restrict__ x, const float* __restrict__ conv_w,
    const float* __restrict__ conv_b, const float* __restrict__ w1,
    const float* __restrict__ lin_w, const float* __restrict__ lin_b,
    float* __restrict__ out)
{
    __shared__ Sm sm;
    const int t    = threadIdx.x;
    const int lane = t & 31;
    const int b    = blockIdx.x;

    // ---------------- precompute weight tables (per CTA, cheap) ----------------
    for (int idx = t; idx < 144; idx += NT) {
        int n = idx / 72, r = idx % 72, g = r / 12, w = r % 12;
        int i = g >> 1, l = g & 1;
        int base = (((n * 3 + i) * 2 + l) * 12 + w) * 3;
        float th = w1[base + 1];
        float sv, cv; __sincosf(0.5f * th, &sv, &cv);
        sm.csT[n][g][w] = make_float2(cv, sv);
        float a = w1[base + 0];                 // phi of current sublayer
        if (g > 0) {
            int ip = (g - 1) >> 1, lp = (g - 1) & 1;
            a += w1[(((n * 3 + ip) * 2 + lp) * 12 + w) * 3 + 2];  // omega of prev
        }
        sm.aS[n][g][w] = a;
    }
    if (t < 108) sm.cwS[t] = conv_w[t];
    if (t < 12)  sm.cbS[t] = conv_b[t];

    // image to smem
    const float* xb = x + (size_t)b * 1024;
    for (int i = t; i < 1024; i += NT) sm.sbuf[i] = xb[i];
    __syncthreads();

    // ---------------- conv (3x3, stride 2, pad 1) + global avg pool ------------
    {
        float acc[QW];
#pragma unroll
        for (int c = 0; c < QW; c++) acc[c] = 0.f;
        for (int pos = t; pos < 256; pos += NT) {
            int oh = pos >> 4, ow = pos & 15;
#pragma unroll
            for (int kh = 0; kh < 3; kh++) {
                int r2 = 2 * oh + kh - 1;
                if ((unsigned)r2 < 32u) {
#pragma unroll
                    for (int kw = 0; kw < 3; kw++) {
                        int c2 = 2 * ow + kw - 1;
                        if ((unsigned)c2 < 32u) {
                            float v = sm.sbuf[r2 * 32 + c2];
#pragma unroll
                            for (int c = 0; c < QW; c++)
                                acc[c] = fmaf(sm.cwS[c * 9 + kh * 3 + kw], v, acc[c]);
                        }
                    }
                }
            }
        }
        reduce12(sm, acc, t, lane, 1.f / 256.f, true);   // -> sm.ang (angles)
    }

    // ---------------- circuit blocks ----------------
    float2 amp[V];
    for (int n = 0; n < 2; n++) {
#pragma unroll
        for (int k = 0; k < V; k++) amp[k] = make_float2(0.f, 0.f);
        if (t == 0) amp[0].x = 1.f;

        for (int g = 0; g < 6; g++) {
            // ---- fused diagonal: [omega_prev +] enc? + phi_cur, with CZ sign ----
            const float* aSp = sm.aS[n][g];
            const bool addI = ((g & 1) == 0);                 // enc at g = 0,2,4
            const int  czr  = (g == 0) ? 0 : ((((g - 1) & 1) == 0) ? 1 : 2);
            __syncthreads();
            if (t < 32) {
                float pk = 0.f;
#pragma unroll
                for (int p = 0; p < 5; p++) {
                    float a = aSp[11 - p] + (addI ? sm.ang[11 - p] : 0.f);
                    pk += a * ((float)((t >> p) & 1) - 0.5f);
                }
                float sv, cv; __sincosf(pk, &sv, &cv);
                sm.eK[t] = make_float2(cv, sv);
            }
            __syncthreads();
            float pt = 0.f;
#pragma unroll
            for (int p = 5; p < 12; p++) {
                float a = aSp[11 - p] + (addI ? sm.ang[11 - p] : 0.f);
                pt += a * ((float)((t >> (p - 5)) & 1) - 0.5f);
            }
            float sv, cv; __sincosf(pt, &sv, &cv);
            float2 et = make_float2(cv, sv);
            const int shi = t << 5;
#pragma unroll
            for (int k = 0; k < V; k++) {
                float2 d = cmulf(et, sm.eK[k]);
                if (czr) {
                    int s12 = shi | k;
                    int rr  = ((s12 << czr) | (s12 >> (12 - czr))) & 0xFFF;
                    if (__popc(s12 & rr) & 1) { d.x = -d.x; d.y = -d.y; }
                }
                amp[k] = cmulf(amp[k], d);
            }

            // ---- 12 real RY butterflies (wires commute; order free) ----
            const float2* cs = sm.csT[n][g];
            ry_local<1 >(amp, cs[11]);
            ry_local<2 >(amp, cs[10]);
            ry_local<4 >(amp, cs[9]);
            ry_local<8 >(amp, cs[8]);
            ry_local<16>(amp, cs[7]);
            ry_lane(amp, 1,  cs[6], lane);
            ry_lane(amp, 2,  cs[5], lane);
            ry_lane(amp, 4,  cs[4], lane);
            ry_lane(amp, 8,  cs[3], lane);
            ry_lane(amp, 16, cs[2], lane);
            ry_warp(amp, 32, cs[1], t, sm.sbuf);
            ry_warp(amp, 64, cs[0], t, sm.sbuf);
        }

        // ---- measure: expval PauliZ per wire (trailing diag/CZ drop out) ----
        {
            float S = 0.f, sp0 = 0.f, sp1 = 0.f, sp2 = 0.f, sp3 = 0.f, sp4 = 0.f;
#pragma unroll
            for (int k = 0; k < V; k++) {
                float pr = fmaf(amp[k].x, amp[k].x, amp[k].y * amp[k].y);
                S += pr;
                sp0 += (k & 1)  ? -pr : pr;
                sp1 += (k & 2)  ? -pr : pr;
                sp2 += (k & 4)  ? -pr : pr;
                sp3 += (k & 8)  ? -pr : pr;
                sp4 += (k & 16) ? -pr : pr;
            }
            float part[QW];
            part[11] = sp0; part[10] = sp1; part[9] = sp2; part[8] = sp3; part[7] = sp4;
#pragma unroll
            for (int p = 5; p < 12; p++)
                part[11 - p] = ((t >> (p - 5)) & 1) ? -S : S;
            __syncthreads();
            reduce12(sm, part, t, lane, 1.f, false);      // -> sm.ang (next inputs)
        }
    }

    // ---------------- linear head: out = expvals @ lin_w.T + lin_b -------------
    for (int m = t; m < 1024; m += NT) {
        float acc = lin_b[m];
#pragma unroll
        for (int j = 0; j < QW; j++) acc = fmaf(sm.ang[j], lin_w[m * 12 + j], acc);
        out[(size_t)b * 1024 + m] = acc;
    }
}

extern "C" void kernel_launch(void* const* d_in, const int* in_sizes, int n_in,
                              void* d_out, int out_size) {
    const float* x      = (const float*)d_in[0];
    const float* conv_w = (const float*)d_in[1];
    const float* conv_b = (const float*)d_in[2];
    const float* w1     = (const float*)d_in[3];
    const float* lin_w  = (const float*)d_in[4];
    const float* lin_b  = (const float*)d_in[5];
    float* out = (float*)d_out;
    int B = in_sizes[0] / 1024;   // x is (B,1,32,32)
    qiddm_kernel<<<B, NT>>>(x, conv_w, conv_b, w1, lin_w, lin_b, out);
}

// round 3
// speedup vs baseline: 1.2633x; 1.2633x over previous
#include <cuda_runtime.h>

#define QW   12
#define DIMS 4096
#define NT   128
#define V    32

// Layout A: s = (t<<5) | k        (k: s-bits 0..4, lane: s5..9, warp: s10,11)
// Layout B: s = (t&31) | (k<<5) | ((t>>5)<<10)   (k: s5..9, lane: s0..4, warp: s10,11)
// wire j <-> s-bit (11-j). Warp bits (s10,s11) = wires 1,0 in BOTH layouts.

__device__ __forceinline__ float2 cmulf(float2 a, float2 b) {
    return make_float2(fmaf(a.x, b.x, -a.y * b.y), fmaf(a.x, b.y, a.y * b.x));
}

struct Sm {
    float2 xch[DIMS];        // 32KB exchange / image buffer
    float2 tab[512];         // diag tables: 16 sign-variants x 32 k-entries
    float2 csT[2][6][12];    // (cos(th/2), sin(th/2))
    float2 uvT[2][6][12];    // (-tan(th/4), sin(th/2)) lifting coeffs
    float  aS[2][6][12];     // static diag alpha per group/wire
    float  aw[12];           // current group's alpha (static + enc)
    float  ang[12];
    float  red[48];
    float  cwS[108];
    float  cbS[12];
    float  kinit[32];
};

template<int M>
__device__ __forceinline__ void ry_lift(float2* amp, float2 uv) {
    const float u = uv.x, v = uv.y;
#pragma unroll
    for (int k = 0; k < V; k++) {
        if (!(k & M)) {
            float2 a = amp[k], b = amp[k | M];
            a.x = fmaf(u, b.x, a.x); a.y = fmaf(u, b.y, a.y);
            b.x = fmaf(v, a.x, b.x); b.y = fmaf(v, a.y, b.y);
            a.x = fmaf(u, b.x, a.x); a.y = fmaf(u, b.y, a.y);
            amp[k] = a; amp[k | M] = b;
        }
    }
}

__device__ __forceinline__ void reduce12(Sm& sm, float* part, int t, int lane,
                                         float scale, bool addBias) {
#pragma unroll
    for (int j = 0; j < QW; j++) {
        float v = part[j];
        v += __shfl_down_sync(0xffffffffu, v, 16);
        v += __shfl_down_sync(0xffffffffu, v, 8);
        v += __shfl_down_sync(0xffffffffu, v, 4);
        v += __shfl_down_sync(0xffffffffu, v, 2);
        v += __shfl_down_sync(0xffffffffu, v, 1);
        if (lane == 0) sm.red[(t >> 5) * QW + j] = v;
    }
    __syncthreads();
    if (t < QW) {
        float v = sm.red[t] + sm.red[QW + t] + sm.red[2 * QW + t] + sm.red[3 * QW + t];
        v *= scale;
        if (addBias) v += sm.cbS[t];
        sm.ang[t] = v;
    }
    __syncthreads();
}

__global__ void __launch_bounds__(NT) qiddm_kernel(
    const float* __restrict__ x, const float* __restrict__ conv_w,
    const float* __restrict__ conv_b, const float* __restrict__ w1,
    const float* __restrict__ lin_w, const float* __restrict__ lin_b,
    float* __restrict__ out)
{
    __shared__ Sm sm;
    const int t    = threadIdx.x;
    const int lane = t & 31;
    const int wh   = (t >> 5) << 5;
    const int b    = blockIdx.x;

    // ---------------- weight tables ----------------
    for (int idx = t; idx < 144; idx += NT) {
        int n = idx / 72, r = idx % 72, g = r / 12, w = r % 12;
        int i = g >> 1, l = g & 1;
        int base = (((n * 3 + i) * 2 + l) * 12 + w) * 3;
        float th = w1[base + 1];
        float sv, cv; __sincosf(0.5f * th, &sv, &cv);
        sm.csT[n][g][w] = make_float2(cv, sv);
        sm.uvT[n][g][w] = make_float2(-__tanf(0.25f * th), sv);
        float a = w1[base + 0];
        if (g > 0) {
            int ip = (g - 1) >> 1, lp = (g - 1) & 1;
            a += w1[(((n * 3 + ip) * 2 + lp) * 12 + w) * 3 + 2];
        }
        sm.aS[n][g][w] = a;
    }
    if (t < 108) sm.cwS[t] = conv_w[t];
    if (t < 12)  sm.cbS[t] = conv_b[t];

    float* img = (float*)sm.xch;
    const float* xb = x + (size_t)b * 1024;
    for (int i = t; i < 1024; i += NT) img[i] = xb[i];
    __syncthreads();

    // ---------------- conv 3x3 s2 p1 + global avg pool ----------------
    {
        float acc[QW];
#pragma unroll
        for (int c = 0; c < QW; c++) acc[c] = 0.f;
        for (int pos = t; pos < 256; pos += NT) {
            int oh = pos >> 4, ow = pos & 15;
#pragma unroll
            for (int kh = 0; kh < 3; kh++) {
                int r2 = 2 * oh + kh - 1;
                if ((unsigned)r2 < 32u) {
#pragma unroll
                    for (int kw = 0; kw < 3; kw++) {
                        int c2 = 2 * ow + kw - 1;
                        if ((unsigned)c2 < 32u) {
                            float v = img[r2 * 32 + c2];
#pragma unroll
                            for (int c = 0; c < QW; c++)
                                acc[c] = fmaf(sm.cwS[c * 9 + kh * 3 + kw], v, acc[c]);
                        }
                    }
                }
            }
        }
        __syncthreads();
        reduce12(sm, acc, t, lane, 1.f / 256.f, true);
    }

    // ---------------- circuit blocks ----------------
    float2 amp[V];
    for (int n = 0; n < 2; n++) {
        // g=0 skipped: diag on |0> is global phase; 12 RYs on |0> = product state (layout A, real)
        const float2* cs0 = sm.csT[n][0];
        if (t < 32) {
            float p = 1.f;
#pragma unroll
            for (int i = 0; i < 5; i++) p *= ((t >> i) & 1) ? cs0[11 - i].y : cs0[11 - i].x;
            sm.kinit[t] = p;
        }
        __syncthreads();
        float tpp = 1.f;
#pragma unroll
        for (int i = 0; i < 7; i++) tpp *= ((t >> i) & 1) ? cs0[6 - i].y : cs0[6 - i].x;
#pragma unroll
        for (int k = 0; k < V; k++) amp[k] = make_float2(tpp * sm.kinit[k], 0.f);

        for (int g = 1; g < 6; g++) {
            const bool layA = (g & 1);           // diag layout: A for g odd, B for g even
            const int  r    = layA ? 1 : 2;      // CZ ring range of previous sublayer
            const bool addI = ((g & 1) == 0);    // enc folded at g = 2, 4

            __syncthreads();
            if (t < 12) sm.aw[t] = sm.aS[n][g][t] + (addI ? sm.ang[t] : 0.f);
            __syncthreads();

            // ---- build sign-folded diag table (k part + CZ k-internal + cross) ----
            const int nent = (r == 1) ? 128 : 512;
            for (int idx = t; idx < nent; idx += NT) {
                int v = idx >> 5, k = idx & 31;
                float ph = 0.f;
#pragma unroll
                for (int i = 0; i < 5; i++) {
                    int w = layA ? (11 - i) : (6 - i);
                    ph += sm.aw[w] * ((float)((k >> i) & 1) - 0.5f);
                }
                int par;
                if (r == 1)
                    par = __popc(k & (k >> 1) & 0xF) ^ ((v & (k >> 4)) & 1) ^ (((v >> 1) & k) & 1);
                else
                    par = __popc(k & (k >> 2) & 0x7) ^ ((v & k) & 1) ^ (((v >> 1) & (k >> 1)) & 1)
                        ^ (((v >> 2) & (k >> 3)) & 1) ^ (((v >> 3) & (k >> 4)) & 1);
                float sv, cv; __sincosf(ph, &sv, &cv);
                float sg = (par & 1) ? -1.f : 1.f;
                sm.tab[idx] = make_float2(cv * sg, sv * sg);
            }

            // ---- per-thread phase (t part) + CZ t-internal sign + variant index ----
            float pt = 0.f;
            int ptpar, vv;
            if (layA) {
#pragma unroll
                for (int i = 0; i < 7; i++) pt += sm.aw[6 - i] * ((float)((t >> i) & 1) - 0.5f);
                ptpar = __popc(t & (t >> 1) & 0x3F);
                vv    = (t & 1) | (((t >> 6) & 1) << 1);
            } else {
#pragma unroll
                for (int i = 0; i < 5; i++) pt += sm.aw[11 - i] * ((float)((t >> i) & 1) - 0.5f);
                pt += sm.aw[1] * ((float)((t >> 5) & 1) - 0.5f);
                pt += sm.aw[0] * ((float)((t >> 6) & 1) - 0.5f);
                ptpar = __popc(t & (t >> 2) & 0x7) ^ (((t >> 5) & t) & 1) ^ (((t >> 6) & (t >> 1)) & 1);
                vv    = ((t >> 3) & 1) | (((t >> 4) & 1) << 1) | (((t >> 5) & 1) << 2) | (((t >> 6) & 1) << 3);
            }
            float sv, cv; __sincosf(pt, &sv, &cv);
            if (ptpar & 1) { sv = -sv; cv = -cv; }
            const float2 et = make_float2(cv, sv);
            const float2* tb = &sm.tab[vv << 5];
            __syncthreads();

            // ---- apply diagonal ----
            if (g == 1) {  // state still real after product init
#pragma unroll
                for (int k = 0; k < V; k++) {
                    float2 d = cmulf(et, tb[k]);
                    amp[k] = make_float2(amp[k].x * d.x, amp[k].x * d.y);
                }
            } else {
#pragma unroll
                for (int k = 0; k < V; k++) amp[k] = cmulf(amp[k], cmulf(et, tb[k]));
            }

            // ---- locals set 1 (current k-bits) ----
            const float2* uv = sm.uvT[n][g];
            if (layA) {
                ry_lift<1 >(amp, uv[11]); ry_lift<2 >(amp, uv[10]); ry_lift<4 >(amp, uv[9]);
                ry_lift<8 >(amp, uv[8]);  ry_lift<16>(amp, uv[7]);
            } else {
                ry_lift<1 >(amp, uv[6]);  ry_lift<2 >(amp, uv[5]);  ry_lift<4 >(amp, uv[4]);
                ry_lift<8 >(amp, uv[3]);  ry_lift<16>(amp, uv[2]);
            }

            // ---- smem transpose: swap k-bits <-> lane-bits (XOR swizzle, conflict-free) ----
            if (layA) {  // A -> B
#pragma unroll
                for (int k = 0; k < V; k++) sm.xch[t * 32 + (k ^ lane)] = amp[k];
                __syncthreads();
#pragma unroll
                for (int k = 0; k < V; k++) amp[k] = sm.xch[(k + wh) * 32 + (lane ^ k)];
            } else {     // B -> A
#pragma unroll
                for (int k = 0; k < V; k++) sm.xch[(k + wh) * 32 + (lane ^ k)] = amp[k];
                __syncthreads();
#pragma unroll
                for (int k = 0; k < V; k++) amp[k] = sm.xch[t * 32 + (k ^ lane)];
            }
            __syncthreads();

            // ---- locals set 2 (new k-bits) ----
            if (layA) {
                ry_lift<1 >(amp, uv[6]);  ry_lift<2 >(amp, uv[5]);  ry_lift<4 >(amp, uv[4]);
                ry_lift<8 >(amp, uv[3]);  ry_lift<16>(amp, uv[2]);
            } else {
                ry_lift<1 >(amp, uv[11]); ry_lift<2 >(amp, uv[10]); ry_lift<4 >(amp, uv[9]);
                ry_lift<8 >(amp, uv[8]);  ry_lift<16>(amp, uv[7]);
            }

            // ---- fused radix-4 warp gate (s10 = wire 1, s11 = wire 0) ----
            {
                const float2 cA = sm.csT[n][g][1];   // s10 gate
                const float2 cB = sm.csT[n][g][0];   // s11 gate
                const int b5 = (t >> 5) & 1, b6 = (t >> 6) & 1;
                const float s1e = b5 ? cA.y : -cA.y;
                const float s2e = b6 ? cB.y : -cB.y;
                const float wS  = cA.x * cB.x;
                const float wA  = s1e * cB.x;   // partner t^32
                const float wB  = cA.x * s2e;   // partner t^64
                const float wC  = s1e * s2e;    // partner t^96
                const int tA = t ^ 32, tB = t ^ 64, tC = t ^ 96;
#pragma unroll
                for (int k = 0; k < V; k++) sm.xch[k * NT + t] = amp[k];
                __syncthreads();
#pragma unroll
                for (int k = 0; k < V; k++) {
                    float2 o1 = sm.xch[k * NT + tA];
                    float2 o2 = sm.xch[k * NT + tB];
                    float2 o3 = sm.xch[k * NT + tC];
                    float ax = wS * amp[k].x, ay = wS * amp[k].y;
                    ax = fmaf(wA, o1.x, ax); ay = fmaf(wA, o1.y, ay);
                    ax = fmaf(wB, o2.x, ax); ay = fmaf(wB, o2.y, ay);
                    ax = fmaf(wC, o3.x, ax); ay = fmaf(wC, o3.y, ay);
                    amp[k] = make_float2(ax, ay);
                }
            }
        }

        // ---- measurement (state is in layout B; trailing diag/CZ drop out) ----
        {
            float S = 0.f, q0 = 0.f, q1 = 0.f, q2 = 0.f, q3 = 0.f, q4 = 0.f;
#pragma unroll
            for (int k = 0; k < V; k++) {
                float pr = fmaf(amp[k].x, amp[k].x, amp[k].y * amp[k].y);
                S += pr;
                q0 += (k & 1)  ? -pr : pr;
                q1 += (k & 2)  ? -pr : pr;
                q2 += (k & 4)  ? -pr : pr;
                q3 += (k & 8)  ? -pr : pr;
                q4 += (k & 16) ? -pr : pr;
            }
            float part[QW];
            part[6] = q0; part[5] = q1; part[4] = q2; part[3] = q3; part[2] = q4;  // k-bit i -> wire 6-i
#pragma unroll
            for (int i = 0; i < 5; i++) part[11 - i] = ((t >> i) & 1) ? -S : S;    // lane bit i -> wire 11-i
            part[1] = ((t >> 5) & 1) ? -S : S;                                     // s10 -> wire 1
            part[0] = ((t >> 6) & 1) ? -S : S;                                     // s11 -> wire 0
            __syncthreads();
            reduce12(sm, part, t, lane, 1.f, false);
        }
    }

    // ---------------- linear head ----------------
    for (int m = t; m < 1024; m += NT) {
        float acc = lin_b[m];
#pragma unroll
        for (int j = 0; j < QW; j++) acc = fmaf(sm.ang[j], lin_w[m * 12 + j], acc);
        out[(size_t)b * 1024 + m] = acc;
    }
}

extern "C" void kernel_launch(void* const* d_in, const int* in_sizes, int n_in,
                              void* d_out, int out_size) {
    const float* x      = (const float*)d_in[0];
    const float* conv_w = (const float*)d_in[1];
    const float* conv_b = (const float*)d_in[2];
    const float* w1     = (const float*)d_in[3];
    const float* lin_w  = (const float*)d_in[4];
    const float* lin_b  = (const float*)d_in[5];
    float* out = (float*)d_out;
    int B = in_sizes[0] / 1024;
    qiddm_kernel<<<B, NT>>>(x, conv_w, conv_b, w1, lin_w, lin_b, out);
}